// round 16
// baseline (speedup 1.0000x reference)
#include <cuda_runtime.h>
#include <cstdint>

#define HW 2
#define H 512
#define W 512

// ---- geometry: 4-wide x 8-tall per thread, direct gmem ----
#define GTX 8                        // threads x (each covers 4 px)
#define GTY 8                        // threads y
#define FPPT 8                       // pixel rows per thread
#define GBLKX 32                     // px per block in x
#define GBLKY (GTY * FPPT)           // 64 px per block in y

typedef unsigned long long u64;

// scratch (allocation-free rule -> device globals)
__device__ float g_buf0[32 * H * W];
__device__ float g_buf1[32 * H * W];

__device__ __forceinline__ float ex2_approx(float x) {
    float y;
    asm("ex2.approx.ftz.f32 %0, %1;" : "=f"(y) : "f"(x));
    return y;
}

// packed f32x2 helpers (Blackwell FFMA2/FADD2/FMUL2 — only reachable via PTX)
__device__ __forceinline__ u64 pack2(float lo, float hi) {
    u64 r;
    asm("mov.b64 %0, {%1, %2};" : "=l"(r) : "f"(lo), "f"(hi));
    return r;
}
__device__ __forceinline__ void unpack2(u64 v, float& lo, float& hi) {
    asm("mov.b64 {%0, %1}, %2;" : "=f"(lo), "=f"(hi) : "l"(v));
}
__device__ __forceinline__ u64 fma2(u64 a, u64 b, u64 c) {
    u64 r;
    asm("fma.rn.f32x2 %0, %1, %2, %3;" : "=l"(r) : "l"(a), "l"(b), "l"(c));
    return r;
}
__device__ __forceinline__ u64 add2(u64 a, u64 b) {
    u64 r;
    asm("add.rn.f32x2 %0, %1, %2;" : "=l"(r) : "l"(a), "l"(b));
    return r;
}
__device__ __forceinline__ u64 mul2(u64 a, u64 b) {
    u64 r;
    asm("mul.rn.f32x2 %0, %1, %2;" : "=l"(r) : "l"(a), "l"(b));
    return r;
}
__device__ __forceinline__ void prefetch_l1(const float* p) {
    asm volatile("prefetch.global.L1 [%0];" :: "l"(p));
}

// ---------------- single kernel: adaptive 3x3 fast path + cold full-5x5 path ----------------
__global__ __launch_bounds__(GTX * GTY) void bilateral_pass(
    const float* __restrict__ in, float* __restrict__ out,
    const float* __restrict__ sigma_xyz, const float* __restrict__ sigma_r,
    int pass)
{
    const float LOG2E = 1.4426950408889634f;
    const float sx = sigma_xyz[2 * pass + 0];
    const float sy = sigma_xyz[2 * pass + 1];
    const float sr = sigma_r[pass];

    const float axn = 0.5f / (sx * sx);
    const float ayn = 0.5f / (sy * sy);
    const float axl = axn * LOG2E;               // log2-domain spatial coeffs
    const float ayl = ayn * LOG2E;
    const float ar  = (0.5f / (sr * sr)) * LOG2E;
    const float nar = -ar;
    const float axyl = axl + ayl;

    const int b   = blockIdx.z;
    const int gx0 = blockIdx.x * GBLKX + threadIdx.x * 4;     // first pixel col
    const int gy0 = blockIdx.y * GBLKY + threadIdx.y * FPPT;  // first pixel row
    const float* img = in  + (size_t)b * (H * W);
    float*       op  = out + (size_t)b * (H * W);

    // ---- adaptive truncation decision (uniform across launch) ----
    // error bound for dropping the 16 |d|=2 taps: per tap <= ws * sr * e^{-1/2}; den >= 1.
    {
        const float w1x = __expf(-axn), w4x = __expf(-4.f * axn);
        const float w1y = __expf(-ayn), w4y = __expf(-4.f * ayn);
        const float ring = 2.f * w4x * (1.f + 2.f * w1y + 2.f * w4y)
                         + 2.f * w4y * (1.f + 2.f * w1x);
        if (!(ring * 0.6065307f * sr < 1e-4f)) {
            // -------- cold path: exact full 5x5, direct gmem, minimal registers --------
            #pragma unroll 1
            for (int r = 0; r < FPPT; r++) {
                #pragma unroll 1
                for (int i = 0; i < 4; i++) {
                    const int py = gy0 + r, px = gx0 + i;
                    const float c = img[py * W + px];
                    float num = c, den = 1.0f;
                    #pragma unroll 1
                    for (int dy = -2; dy <= 2; dy++) {
                        const int yy = min(max(py + dy, 0), H - 1);
                        #pragma unroll 1
                        for (int dx = -2; dx <= 2; dx++) {
                            if ((dx | dy) == 0) continue;
                            const int xx = min(max(px + dx, 0), W - 1);
                            const float nb = img[yy * W + xx];
                            const float d  = nb - c;
                            const float s  = fmaf((float)(dx * dx), axl,
                                                  (float)(dy * dy) * ayl);
                            const float w  = ex2_approx(fmaf(d * d, nar, -s));
                            num = fmaf(w, nb, num);
                            den += w;
                        }
                    }
                    op[py * W + px] = __fdividef(num, den);
                }
            }
            return;
        }
    }

    // -------- fast path: 3x3, packed taps + symmetric-edge weight caches --------
    const u64 nar2    = pack2(nar, nar);
    const u64 negone2 = pack2(-1.0f, -1.0f);
    const u64 one2    = pack2(1.0f, 1.0f);
    const u64 ns_xy2  = pack2(-axyl, -axyl);   // |dx|=1,|dy|=1
    const u64 ns_y2   = pack2(-ayl,  -ayl);    // dx=0,|dy|=1
    const u64 ns_x2   = pack2(-axl,  -axl);    // |dx|=1,dy=0

    // clamped edge columns (only ones that can go OOB)
    const int xm1 = max(gx0 - 1, 0);
    const int xp4 = min(gx0 + 4, W - 1);

    // 3-slot row ring, 6 floats per row (cols gx0-1 .. gx0+4)
    float rows[3][6];

    // full clamp (prime only)
    #define LOAD_ROW_CL(SLOT, RY) {                                     \
        const int ryc = min(max((RY), 0), H - 1);                       \
        const float* rp = img + ryc * W;                                \
        const float4 m = *(const float4*)(rp + gx0);                    \
        rows[SLOT][0] = rp[xm1];                                        \
        rows[SLOT][1] = m.x; rows[SLOT][2] = m.y;                       \
        rows[SLOT][3] = m.z; rows[SLOT][4] = m.w;                       \
        rows[SLOT][5] = rp[xp4];                                        \
    }
    // min-only clamp (hot loop; RY >= 1 always)
    #define LOAD_ROW(SLOT, RY) {                                        \
        const int ryc = min((RY), H - 1);                               \
        const float* rp = img + ryc * W;                                \
        const float4 m = *(const float4*)(rp + gx0);                    \
        rows[SLOT][0] = rp[xm1];                                        \
        rows[SLOT][1] = m.x; rows[SLOT][2] = m.y;                       \
        rows[SLOT][3] = m.z; rows[SLOT][4] = m.w;                       \
        rows[SLOT][5] = rp[xp4];                                        \
    }
    // L1 prefetch of a future row (zero register cost; covers L2 latency)
    #define PREFETCH_ROW(RY) {                                          \
        const int ryc = min((RY), H - 1);                               \
        prefetch_l1(img + ryc * W + gx0);                               \
    }

    // prefetch the rows the first two loop iterations will LDG
    PREFETCH_ROW(gy0 + 1)
    PREFETCH_ROW(gy0 + 2)

    // prime: rows gy0-1, gy0 (bot row loads in-loop)
    LOAD_ROW_CL(0, gy0 - 1)
    LOAD_ROW_CL(1, gy0)

    // compute edge weight pair: d = nb - c; w = ex2(nar*d^2 + ns)
    #define EDGE2(W2, NB2, NS2, C2) {                    \
        const u64 d2 = fma2((C2), negone2, (NB2));       \
        const u64 u2 = mul2(d2, nar2);                   \
        const u64 g2 = fma2(d2, u2, (NS2));              \
        float ga, gb;  unpack2(g2, ga, gb);              \
        (W2) = pack2(ex2_approx(ga), ex2_approx(gb));    \
    }
    #define APPLY(W2, NB2, NUM2, DEN2) {                 \
        (NUM2) = fma2((W2), (NB2), (NUM2));              \
        (DEN2) = add2((DEN2), (W2));                     \
    }

    // bot-edge weight cache: w(u, dxc) for u=0..3, dxc=-1,0,+1
    u64 wm1A, w0A, wp1A, wm1B, w0B, wp1B;

    #pragma unroll
    for (int r = 0; r < FPPT; r++) {
        // load this iteration's bottom row (prefetched to L1 two iters ago)
        LOAD_ROW((r + 2) % 3, gy0 + 1 + r)
        // L1-prefetch 2 iterations ahead of the register load above
        if (r < FPPT - 2) PREFETCH_ROW(gy0 + 3 + r)

        const float* top = rows[(r    ) % 3];
        const float* mid = rows[(r + 1) % 3];
        const float* bot = rows[(r + 2) % 3];

        // pair A = px cols 0,1 (mid[1],mid[2]); pair B = px cols 2,3 (mid[3],mid[4])
        const u64 c2A = pack2(mid[1], mid[2]);
        const u64 c2B = pack2(mid[3], mid[4]);

        // center taps (w == 1 exactly) folded into init
        u64 numA = c2A, denA = one2;
        u64 numB = c2B, denB = one2;

        // packed top-row neighbor values
        const u64 t_m1A = pack2(top[0], top[1]);
        const u64 t_0A  = pack2(top[1], top[2]);
        const u64 t_p1A = pack2(top[2], top[3]);
        const u64 t_m1B = t_p1A;                   // (top[2], top[3])
        const u64 t_0B  = pack2(top[3], top[4]);
        const u64 t_p1B = pack2(top[4], top[5]);

        if (r == 0) {
            // first row: all top edges fresh
            u64 w;
            EDGE2(w, t_m1A, ns_xy2, c2A) APPLY(w, t_m1A, numA, denA)
            EDGE2(w, t_0A,  ns_y2,  c2A) APPLY(w, t_0A,  numA, denA)
            EDGE2(w, t_p1A, ns_xy2, c2A) APPLY(w, t_p1A, numA, denA)
            EDGE2(w, t_m1B, ns_xy2, c2B) APPLY(w, t_m1B, numB, denB)
            EDGE2(w, t_0B,  ns_y2,  c2B) APPLY(w, t_0B,  numB, denB)
            EDGE2(w, t_p1B, ns_xy2, c2B) APPLY(w, t_p1B, numB, denB)
        } else {
            // cached top edges (= previous iteration's bot edges, symmetric)
            APPLY(w0A, t_0A, numA, denA)
            APPLY(w0B, t_0B, numB, denB)

            // two boundary edges not in cache: (u=-1,dxc=+1) and (u=4,dxc=-1)
            const float df1 = top[0] - mid[1];
            const float wf1 = ex2_approx(fmaf(df1, df1 * nar, -axyl));
            const float df2 = top[5] - mid[4];
            const float wf2 = ex2_approx(fmaf(df2, df2 * nar, -axyl));

            float m1Alo, m1Ahi, m1Blo, m1Bhi, p1Alo, p1Ahi, p1Blo, p1Bhi;
            unpack2(wm1A, m1Alo, m1Ahi);
            unpack2(wm1B, m1Blo, m1Bhi);
            unpack2(wp1A, p1Alo, p1Ahi);
            unpack2(wp1B, p1Blo, p1Bhi);

            // top dx=-1 taps: weights = cached (u=v-1, dxc=+1)
            { const u64 w2 = pack2(wf1,   p1Alo); APPLY(w2, t_m1A, numA, denA) }
            { const u64 w2 = pack2(p1Ahi, p1Blo); APPLY(w2, t_m1B, numB, denB) }
            // top dx=+1 taps: weights = cached (u=v+1, dxc=-1)
            { const u64 w2 = pack2(m1Ahi, m1Blo); APPLY(w2, t_p1A, numA, denA) }
            { const u64 w2 = pack2(m1Bhi, wf2);   APPLY(w2, t_p1B, numB, denB) }
        }

        // mid-row taps: 5 distinct horizontal edges shared across the 8 taps
        {
            const u64 nbAl = pack2(mid[0], mid[1]);
            const u64 nbAr = pack2(mid[2], mid[3]);
            const u64 nbBr = pack2(mid[4], mid[5]);

            // P = (e(mid0,mid1), e(mid1,mid2))
            const u64 dP = fma2(c2A, negone2, nbAl);
            const u64 gP = fma2(dP, mul2(dP, nar2), ns_x2);
            float gPl, gPh;  unpack2(gP, gPl, gPh);
            const float wPl = ex2_approx(gPl), wPh = ex2_approx(gPh);

            // Q = (e(mid2,mid3), e(mid3,mid4))
            const u64 dQ = fma2(c2B, negone2, nbAr);
            const u64 gQ = fma2(dQ, mul2(dQ, nar2), ns_x2);
            float gQl, gQh;  unpack2(gQ, gQl, gQh);
            const float wQl = ex2_approx(gQl), wQh = ex2_approx(gQh);

            // e(mid4,mid5): scalar
            const float d34 = mid[5] - mid[4];
            const float w34 = ex2_approx(fmaf(d34, d34 * nar, -axl));

            const u64 LA = pack2(wPl, wPh);    // left weights of pair A
            const u64 RA = pack2(wPh, wQl);    // right weights of pair A
            const u64 LB = pack2(wQl, wQh);    // left weights of pair B
            const u64 RB = pack2(wQh, w34);    // right weights of pair B
            APPLY(LA, nbAl, numA, denA)
            APPLY(RA, nbAr, numA, denA)
            APPLY(LB, nbAr, numB, denB)
            APPLY(RB, nbBr, numB, denB)
        }

        // bot-row taps (fresh; cache weights for next iteration's top)
        {
            const u64 b_m1A = pack2(bot[0], bot[1]);
            const u64 b_0A  = pack2(bot[1], bot[2]);
            const u64 b_p1A = pack2(bot[2], bot[3]);
            const u64 b_m1B = b_p1A;
            const u64 b_0B  = pack2(bot[3], bot[4]);
            const u64 b_p1B = pack2(bot[4], bot[5]);
            EDGE2(wm1A, b_m1A, ns_xy2, c2A) APPLY(wm1A, b_m1A, numA, denA)
            EDGE2(w0A,  b_0A,  ns_y2,  c2A) APPLY(w0A,  b_0A,  numA, denA)
            EDGE2(wp1A, b_p1A, ns_xy2, c2A) APPLY(wp1A, b_p1A, numA, denA)
            EDGE2(wm1B, b_m1B, ns_xy2, c2B) APPLY(wm1B, b_m1B, numB, denB)
            EDGE2(w0B,  b_0B,  ns_y2,  c2B) APPLY(w0B,  b_0B,  numB, denB)
            EDGE2(wp1B, b_p1B, ns_xy2, c2B) APPLY(wp1B, b_p1B, numB, denB)
        }

        float n0, n1, n2, n3, d0, d1, d2, d3;
        unpack2(numA, n0, n1); unpack2(denA, d0, d1);
        unpack2(numB, n2, n3); unpack2(denB, d2, d3);
        float4 res;
        res.x = __fdividef(n0, d0);
        res.y = __fdividef(n1, d1);
        res.z = __fdividef(n2, d2);
        res.w = __fdividef(n3, d3);
        *(float4*)(op + (gy0 + r) * W + gx0) = res;
    }
    #undef LOAD_ROW
    #undef LOAD_ROW_CL
    #undef PREFETCH_ROW
    #undef EDGE2
    #undef APPLY
}

extern "C" void kernel_launch(void* const* d_in, const int* in_sizes, int n_in,
                              void* d_out, int out_size)
{
    const float* x         = (const float*)d_in[0];
    const float* sigma_xyz = (const float*)d_in[1];
    const float* sigma_r   = (const float*)d_in[2];
    float* out = (float*)d_out;

    const int B = in_sizes[0] / (H * W);

    float* buf0;
    float* buf1;
    cudaGetSymbolAddress((void**)&buf0, g_buf0);
    cudaGetSymbolAddress((void**)&buf1, g_buf1);

    dim3 fblock(GTX, GTY, 1);
    dim3 fgrid(W / GBLKX, H / GBLKY, B);

    bilateral_pass<<<fgrid, fblock>>>(x,    buf0, sigma_xyz, sigma_r, 0);
    bilateral_pass<<<fgrid, fblock>>>(buf0, buf1, sigma_xyz, sigma_r, 1);
    bilateral_pass<<<fgrid, fblock>>>(buf1, out,  sigma_xyz, sigma_r, 2);
}

// round 17
// speedup vs baseline: 1.0288x; 1.0288x over previous
#include <cuda_runtime.h>
#include <cstdint>

#define HW 2
#define H 512
#define W 512

// ---- geometry: 4-wide x 8-tall per thread, direct gmem ----
#define GTX 16                       // threads x (each covers 4 px)
#define GTY 4                        // threads y
#define FPPT 8                       // pixel rows per thread
#define GBLKX (GTX * 4)              // 64 px per block in x
#define GBLKY (GTY * FPPT)           // 32 px per block in y

typedef unsigned long long u64;

// scratch (allocation-free rule -> device globals)
__device__ float g_buf0[32 * H * W];
__device__ float g_buf1[32 * H * W];

__device__ __forceinline__ float ex2_approx(float x) {
    float y;
    asm("ex2.approx.ftz.f32 %0, %1;" : "=f"(y) : "f"(x));
    return y;
}

// packed f32x2 helpers (Blackwell FFMA2/FADD2/FMUL2 — only reachable via PTX)
__device__ __forceinline__ u64 pack2(float lo, float hi) {
    u64 r;
    asm("mov.b64 %0, {%1, %2};" : "=l"(r) : "f"(lo), "f"(hi));
    return r;
}
__device__ __forceinline__ void unpack2(u64 v, float& lo, float& hi) {
    asm("mov.b64 {%0, %1}, %2;" : "=f"(lo), "=f"(hi) : "l"(v));
}
__device__ __forceinline__ u64 fma2(u64 a, u64 b, u64 c) {
    u64 r;
    asm("fma.rn.f32x2 %0, %1, %2, %3;" : "=l"(r) : "l"(a), "l"(b), "l"(c));
    return r;
}
__device__ __forceinline__ u64 add2(u64 a, u64 b) {
    u64 r;
    asm("add.rn.f32x2 %0, %1, %2;" : "=l"(r) : "l"(a), "l"(b));
    return r;
}
__device__ __forceinline__ u64 mul2(u64 a, u64 b) {
    u64 r;
    asm("mul.rn.f32x2 %0, %1, %2;" : "=l"(r) : "l"(a), "l"(b));
    return r;
}
__device__ __forceinline__ void prefetch_l1(const float* p) {
    asm volatile("prefetch.global.L1 [%0];" :: "l"(p));
}

// ---------------- single kernel: adaptive 3x3 fast path + cold full-5x5 path ----------------
__global__ __launch_bounds__(GTX * GTY) void bilateral_pass(
    const float* __restrict__ in, float* __restrict__ out,
    const float* __restrict__ sigma_xyz, const float* __restrict__ sigma_r,
    int pass)
{
    const float LOG2E = 1.4426950408889634f;
    const float sx = sigma_xyz[2 * pass + 0];
    const float sy = sigma_xyz[2 * pass + 1];
    const float sr = sigma_r[pass];

    const float axn = 0.5f / (sx * sx);
    const float ayn = 0.5f / (sy * sy);
    const float axl = axn * LOG2E;               // log2-domain spatial coeffs
    const float ayl = ayn * LOG2E;
    const float ar  = (0.5f / (sr * sr)) * LOG2E;
    const float nar = -ar;
    const float axyl = axl + ayl;

    const int b   = blockIdx.z;
    const int gx0 = blockIdx.x * GBLKX + threadIdx.x * 4;     // first pixel col
    const int gy0 = blockIdx.y * GBLKY + threadIdx.y * FPPT;  // first pixel row
    const float* img = in  + (size_t)b * (H * W);
    float*       op  = out + (size_t)b * (H * W);

    // ---- adaptive truncation decision (uniform across launch) ----
    // error bound for dropping the 16 |d|=2 taps: per tap <= ws * sr * e^{-1/2}; den >= 1.
    {
        const float w1x = __expf(-axn), w4x = __expf(-4.f * axn);
        const float w1y = __expf(-ayn), w4y = __expf(-4.f * ayn);
        const float ring = 2.f * w4x * (1.f + 2.f * w1y + 2.f * w4y)
                         + 2.f * w4y * (1.f + 2.f * w1x);
        if (!(ring * 0.6065307f * sr < 1e-4f)) {
            // -------- cold path: exact full 5x5, direct gmem, minimal registers --------
            #pragma unroll 1
            for (int r = 0; r < FPPT; r++) {
                #pragma unroll 1
                for (int i = 0; i < 4; i++) {
                    const int py = gy0 + r, px = gx0 + i;
                    const float c = img[py * W + px];
                    float num = c, den = 1.0f;
                    #pragma unroll 1
                    for (int dy = -2; dy <= 2; dy++) {
                        const int yy = min(max(py + dy, 0), H - 1);
                        #pragma unroll 1
                        for (int dx = -2; dx <= 2; dx++) {
                            if ((dx | dy) == 0) continue;
                            const int xx = min(max(px + dx, 0), W - 1);
                            const float nb = img[yy * W + xx];
                            const float d  = nb - c;
                            const float s  = fmaf((float)(dx * dx), axl,
                                                  (float)(dy * dy) * ayl);
                            const float w  = ex2_approx(fmaf(d * d, nar, -s));
                            num = fmaf(w, nb, num);
                            den += w;
                        }
                    }
                    op[py * W + px] = __fdividef(num, den);
                }
            }
            return;
        }
    }

    // -------- fast path: 3x3, packed taps + symmetric-edge weight caches --------
    const u64 nar2    = pack2(nar, nar);
    const u64 negone2 = pack2(-1.0f, -1.0f);
    const u64 one2    = pack2(1.0f, 1.0f);
    const u64 ns_xy2  = pack2(-axyl, -axyl);   // |dx|=1,|dy|=1
    const u64 ns_y2   = pack2(-ayl,  -ayl);    // dx=0,|dy|=1
    const u64 ns_x2   = pack2(-axl,  -axl);    // |dx|=1,dy=0

    // clamped edge columns (only ones that can go OOB)
    const int xm1 = max(gx0 - 1, 0);
    const int xp4 = min(gx0 + 4, W - 1);

    // 4-slot row ring, 6 floats per row (cols gx0-1 .. gx0+4)
    float rows[4][6];

    #define LOAD_ROW(SLOT, RY) {                                        \
        const int ryc = min(max((RY), 0), H - 1);                       \
        const float* rp = img + ryc * W;                                \
        const float4 m = *(const float4*)(rp + gx0);                    \
        rows[SLOT][0] = rp[xm1];                                        \
        rows[SLOT][1] = m.x; rows[SLOT][2] = m.y;                       \
        rows[SLOT][3] = m.z; rows[SLOT][4] = m.w;                       \
        rows[SLOT][5] = rp[xp4];                                        \
    }
    // L1 prefetch of a future row (zero register cost; covers L2 latency)
    #define PREFETCH_ROW(RY) {                                          \
        const int ryc = min((RY), H - 1);                               \
        prefetch_l1(img + ryc * W + gx0);                               \
    }

    // prefetch the rows the first two loop iterations will LDG
    PREFETCH_ROW(gy0 + 2)
    PREFETCH_ROW(gy0 + 3)

    // prime: rows gy0-1, gy0, gy0+1
    LOAD_ROW(0, gy0 - 1)
    LOAD_ROW(1, gy0)
    LOAD_ROW(2, gy0 + 1)

    // compute edge weight pair: d = nb - c; w = ex2(nar*d^2 + ns)
    #define EDGE2(W2, NB2, NS2, C2) {                    \
        const u64 d2 = fma2((C2), negone2, (NB2));       \
        const u64 u2 = mul2(d2, nar2);                   \
        const u64 g2 = fma2(d2, u2, (NS2));              \
        float ga, gb;  unpack2(g2, ga, gb);              \
        (W2) = pack2(ex2_approx(ga), ex2_approx(gb));    \
    }
    #define APPLY(W2, NB2, NUM2, DEN2) {                 \
        (NUM2) = fma2((W2), (NB2), (NUM2));              \
        (DEN2) = add2((DEN2), (W2));                     \
    }

    // bot-edge weight cache: w(u, dxc) for u=0..3, dxc=-1,0,+1
    u64 wm1A, w0A, wp1A, wm1B, w0B, wp1B;

    #pragma unroll
    for (int r = 0; r < FPPT; r++) {
        // L1-prefetch 2 iterations ahead of the register load below
        if (r < FPPT - 3) PREFETCH_ROW(gy0 + 4 + r)
        // register prefetch: next bottom row (one iteration ahead; L1 hit)
        if (r < FPPT - 1) LOAD_ROW((r + 3) & 3, gy0 + 2 + r)

        const float* top = rows[(r    ) & 3];
        const float* mid = rows[(r + 1) & 3];
        const float* bot = rows[(r + 2) & 3];

        // pair A = px cols 0,1 (mid[1],mid[2]); pair B = px cols 2,3 (mid[3],mid[4])
        const u64 c2A = pack2(mid[1], mid[2]);
        const u64 c2B = pack2(mid[3], mid[4]);

        // center taps (w == 1 exactly) folded into init
        u64 numA = c2A, denA = one2;
        u64 numB = c2B, denB = one2;

        // packed top-row neighbor values
        const u64 t_m1A = pack2(top[0], top[1]);
        const u64 t_0A  = pack2(top[1], top[2]);
        const u64 t_p1A = pack2(top[2], top[3]);
        const u64 t_m1B = t_p1A;                   // (top[2], top[3])
        const u64 t_0B  = pack2(top[3], top[4]);
        const u64 t_p1B = pack2(top[4], top[5]);

        if (r == 0) {
            // first row: all top edges fresh
            u64 w;
            EDGE2(w, t_m1A, ns_xy2, c2A) APPLY(w, t_m1A, numA, denA)
            EDGE2(w, t_0A,  ns_y2,  c2A) APPLY(w, t_0A,  numA, denA)
            EDGE2(w, t_p1A, ns_xy2, c2A) APPLY(w, t_p1A, numA, denA)
            EDGE2(w, t_m1B, ns_xy2, c2B) APPLY(w, t_m1B, numB, denB)
            EDGE2(w, t_0B,  ns_y2,  c2B) APPLY(w, t_0B,  numB, denB)
            EDGE2(w, t_p1B, ns_xy2, c2B) APPLY(w, t_p1B, numB, denB)
        } else {
            // cached top edges (= previous iteration's bot edges, symmetric)
            APPLY(w0A, t_0A, numA, denA)
            APPLY(w0B, t_0B, numB, denB)

            // two boundary edges not in cache: (u=-1,dxc=+1) and (u=4,dxc=-1)
            const float df1 = top[0] - mid[1];
            const float wf1 = ex2_approx(fmaf(df1, df1 * nar, -axyl));
            const float df2 = top[5] - mid[4];
            const float wf2 = ex2_approx(fmaf(df2, df2 * nar, -axyl));

            float m1Alo, m1Ahi, m1Blo, m1Bhi, p1Alo, p1Ahi, p1Blo, p1Bhi;
            unpack2(wm1A, m1Alo, m1Ahi);
            unpack2(wm1B, m1Blo, m1Bhi);
            unpack2(wp1A, p1Alo, p1Ahi);
            unpack2(wp1B, p1Blo, p1Bhi);

            // top dx=-1 taps: weights = cached (u=v-1, dxc=+1)
            { const u64 w2 = pack2(wf1,   p1Alo); APPLY(w2, t_m1A, numA, denA) }
            { const u64 w2 = pack2(p1Ahi, p1Blo); APPLY(w2, t_m1B, numB, denB) }
            // top dx=+1 taps: weights = cached (u=v+1, dxc=-1)
            { const u64 w2 = pack2(m1Ahi, m1Blo); APPLY(w2, t_p1A, numA, denA) }
            { const u64 w2 = pack2(m1Bhi, wf2);   APPLY(w2, t_p1B, numB, denB) }
        }

        // mid-row taps: 5 distinct horizontal edges shared across the 8 taps
        {
            const u64 nbAl = pack2(mid[0], mid[1]);
            const u64 nbAr = pack2(mid[2], mid[3]);
            const u64 nbBr = pack2(mid[4], mid[5]);

            // P = (e(mid0,mid1), e(mid1,mid2))
            const u64 dP = fma2(c2A, negone2, nbAl);
            const u64 gP = fma2(dP, mul2(dP, nar2), ns_x2);
            float gPl, gPh;  unpack2(gP, gPl, gPh);
            const float wPl = ex2_approx(gPl), wPh = ex2_approx(gPh);

            // Q = (e(mid2,mid3), e(mid3,mid4))
            const u64 dQ = fma2(c2B, negone2, nbAr);
            const u64 gQ = fma2(dQ, mul2(dQ, nar2), ns_x2);
            float gQl, gQh;  unpack2(gQ, gQl, gQh);
            const float wQl = ex2_approx(gQl), wQh = ex2_approx(gQh);

            // e(mid4,mid5): scalar
            const float d34 = mid[5] - mid[4];
            const float w34 = ex2_approx(fmaf(d34, d34 * nar, -axl));

            const u64 LA = pack2(wPl, wPh);    // left weights of pair A
            const u64 RA = pack2(wPh, wQl);    // right weights of pair A
            const u64 LB = pack2(wQl, wQh);    // left weights of pair B
            const u64 RB = pack2(wQh, w34);    // right weights of pair B
            APPLY(LA, nbAl, numA, denA)
            APPLY(RA, nbAr, numA, denA)
            APPLY(LB, nbAr, numB, denB)
            APPLY(RB, nbBr, numB, denB)
        }

        // bot-row taps (fresh; cache weights for next iteration's top)
        {
            const u64 b_m1A = pack2(bot[0], bot[1]);
            const u64 b_0A  = pack2(bot[1], bot[2]);
            const u64 b_p1A = pack2(bot[2], bot[3]);
            const u64 b_m1B = b_p1A;
            const u64 b_0B  = pack2(bot[3], bot[4]);
            const u64 b_p1B = pack2(bot[4], bot[5]);
            EDGE2(wm1A, b_m1A, ns_xy2, c2A) APPLY(wm1A, b_m1A, numA, denA)
            EDGE2(w0A,  b_0A,  ns_y2,  c2A) APPLY(w0A,  b_0A,  numA, denA)
            EDGE2(wp1A, b_p1A, ns_xy2, c2A) APPLY(wp1A, b_p1A, numA, denA)
            EDGE2(wm1B, b_m1B, ns_xy2, c2B) APPLY(wm1B, b_m1B, numB, denB)
            EDGE2(w0B,  b_0B,  ns_y2,  c2B) APPLY(w0B,  b_0B,  numB, denB)
            EDGE2(wp1B, b_p1B, ns_xy2, c2B) APPLY(wp1B, b_p1B, numB, denB)
        }

        float n0, n1, n2, n3, d0, d1, d2, d3;
        unpack2(numA, n0, n1); unpack2(denA, d0, d1);
        unpack2(numB, n2, n3); unpack2(denB, d2, d3);
        float4 res;
        res.x = __fdividef(n0, d0);
        res.y = __fdividef(n1, d1);
        res.z = __fdividef(n2, d2);
        res.w = __fdividef(n3, d3);
        *(float4*)(op + (gy0 + r) * W + gx0) = res;
    }
    #undef LOAD_ROW
    #undef PREFETCH_ROW
    #undef EDGE2
    #undef APPLY
}

extern "C" void kernel_launch(void* const* d_in, const int* in_sizes, int n_in,
                              void* d_out, int out_size)
{
    const float* x         = (const float*)d_in[0];
    const float* sigma_xyz = (const float*)d_in[1];
    const float* sigma_r   = (const float*)d_in[2];
    float* out = (float*)d_out;

    const int B = in_sizes[0] / (H * W);

    float* buf0;
    float* buf1;
    cudaGetSymbolAddress((void**)&buf0, g_buf0);
    cudaGetSymbolAddress((void**)&buf1, g_buf1);

    dim3 fblock(GTX, GTY, 1);
    dim3 fgrid(W / GBLKX, H / GBLKY, B);

    bilateral_pass<<<fgrid, fblock>>>(x,    buf0, sigma_xyz, sigma_r, 0);
    bilateral_pass<<<fgrid, fblock>>>(buf0, buf1, sigma_xyz, sigma_r, 1);
    bilateral_pass<<<fgrid, fblock>>>(buf1, out,  sigma_xyz, sigma_r, 2);
}